// round 7
// baseline (speedup 1.0000x reference)
#include <cuda_runtime.h>
#include <cuda_bf16.h>
#include <cstdint>

#define BB 4
#define NTOK 32768
#define CC 256
#define HH 8
#define DD 64
#define GG 64
#define INNER 512
#define TOK (BB*NTOK)   // 131072

// ---------------- scratch (device globals; no runtime allocation) ----------------
__device__ __align__(16) __nv_bfloat16 g_x_hi[(size_t)TOK*CC];   // x split bf16 [tok][c]
__device__ __align__(16) __nv_bfloat16 g_x_lo[(size_t)TOK*CC];
__device__ __align__(16) __nv_bfloat16 g_xT_hi[(size_t)BB*CC*NTOK]; // x^T [b][c][n]
__device__ __align__(16) __nv_bfloat16 g_xT_lo[(size_t)BB*CC*NTOK];
__device__ __align__(16) __nv_bfloat16 g_w_hi[(size_t)TOK*INNER];// slice weights [tok][hg]
__device__ __align__(16) __nv_bfloat16 g_w_lo[(size_t)TOK*INNER];
__device__ __align__(16) __nv_bfloat16 g_wT_hi[(size_t)BB*HH*GG*NTOK]; // w^T [bh][g][n]
__device__ __align__(16) __nv_bfloat16 g_wT_lo[(size_t)BB*HH*GG*NTOK];
__device__ __align__(16) __nv_bfloat16 g_wslT_hi[INNER*CC];      // (Wx@Wslice)^T split
__device__ __align__(16) __nv_bfloat16 g_wslT_lo[INNER*CC];
__device__ float g_bsl[INNER];                    // folded slice bias
__device__ float g_P[BB*HH*GG*CC];                // pooled P[bh][g][c] (atomic accum)
__device__ float g_st[BB*HH*GG*DD];               // slice token sums
__device__ float g_norm[BB*HH*GG];                // weight column sums
__device__ float g_os[BB*HH*GG*DD];               // out_slice
__device__ __align__(16) __nv_bfloat16 g_weffT_hi[BB*CC*INNER];  // W_eff^T [b][n=256][k=512]
__device__ __align__(16) __nv_bfloat16 g_weffT_lo[BB*CC*INNER];

// ============================ helpers ============================
#define DINLINE __device__ __forceinline__

DINLINE uint32_t smem_u32(const void* p) {
    uint32_t a;
    asm("{ .reg .u64 t; cvta.to.shared.u64 t, %1; cvt.u32.u64 %0, t; }" : "=r"(a) : "l"(p));
    return a;
}
DINLINE void cpa16(uint32_t dst, const void* src) {
    asm volatile("cp.async.ca.shared.global [%0], [%1], 16;" :: "r"(dst), "l"(src));
}
#define CP_COMMIT() asm volatile("cp.async.commit_group;" ::: "memory")
#define CP_WAIT1()  asm volatile("cp.async.wait_group 1;" ::: "memory")
#define CP_WAIT0()  asm volatile("cp.async.wait_group 0;" ::: "memory")

DINLINE void ldsm4(uint32_t* r, uint32_t addr) {
    asm volatile("ldmatrix.sync.aligned.m8n8.x4.shared.b16 {%0,%1,%2,%3}, [%4];"
        : "=r"(r[0]), "=r"(r[1]), "=r"(r[2]), "=r"(r[3]) : "r"(addr));
}
DINLINE void mma_bf16(float* d, uint32_t a0, uint32_t a1, uint32_t a2, uint32_t a3,
                      uint32_t b0, uint32_t b1) {
    asm volatile("mma.sync.aligned.m16n8k16.row.col.f32.bf16.bf16.f32 "
        "{%0,%1,%2,%3}, {%4,%5,%6,%7}, {%8,%9}, {%0,%1,%2,%3};"
        : "+f"(d[0]), "+f"(d[1]), "+f"(d[2]), "+f"(d[3])
        : "r"(a0), "r"(a1), "r"(a2), "r"(a3), "r"(b0), "r"(b1));
}
#define SWZ(off)   ((off) ^ (((off) >> 3) & 0x70))
#define SWZ64(off) ((off) ^ (((off) >> 3) & 0x30))
#define STG 132        // stage row stride (floats)
#define GSMEM 98304    // 3 stages x 32KB (Ahi,Alo,Bhi,Blo 8KB each)
#define PGSMEM 73728   // 3 stages x 24KB (Ahi,Alo 4KB; Bhi,Blo 8KB)

// ---------------- zero accumulators (must run every graph replay) ----------------
__global__ void k_zero() {
    int i = blockIdx.x * blockDim.x + threadIdx.x;
    if (i < BB*HH*GG*CC) g_P[i] = 0.f;
    if (i < BB*HH*GG)    g_norm[i] = 0.f;
}

// ---------------- split x into bf16 hi/lo, both [tok][c] and transposed ----------------
__global__ void k_split(const float* __restrict__ x) {
    __shared__ uint16_t shi[64][68], slo[64][68];
    int tid = threadIdx.x;
    size_t t0 = (size_t)blockIdx.x * 64;     // token tile
    int c0 = blockIdx.y * 64;                // c tile
    int r = tid >> 2, cq = (tid & 3) * 16;
    #pragma unroll
    for (int j = 0; j < 16; j += 4) {
        float4 v = *(const float4*)&x[(t0 + r) * CC + c0 + cq + j];
        __nv_bfloat16 hx = __float2bfloat16(v.x), hy = __float2bfloat16(v.y);
        __nv_bfloat16 hz = __float2bfloat16(v.z), hw = __float2bfloat16(v.w);
        __nv_bfloat162 h01(hx, hy), h23(hz, hw);
        __nv_bfloat162 l01 = __floats2bfloat162_rn(v.x - __bfloat162float(hx),
                                                   v.y - __bfloat162float(hy));
        __nv_bfloat162 l23 = __floats2bfloat162_rn(v.z - __bfloat162float(hz),
                                                   v.w - __bfloat162float(hw));
        uint2 uh, ul;
        uh.x = *reinterpret_cast<uint32_t*>(&h01); uh.y = *reinterpret_cast<uint32_t*>(&h23);
        ul.x = *reinterpret_cast<uint32_t*>(&l01); ul.y = *reinterpret_cast<uint32_t*>(&l23);
        *(uint2*)&g_x_hi[(t0 + r) * CC + c0 + cq + j] = uh;
        *(uint2*)&g_x_lo[(t0 + r) * CC + c0 + cq + j] = ul;
        *(uint2*)&shi[r][cq + j] = uh;
        *(uint2*)&slo[r][cq + j] = ul;
    }
    __syncthreads();
    int c = tid >> 2, tq = (tid & 3) * 16;
    size_t b = t0 >> 15;                 // /NTOK
    size_t nloc = t0 & (NTOK - 1);
    size_t base = ((size_t)b * CC + c0 + c) * NTOK + nloc + tq;
    #pragma unroll
    for (int j = 0; j < 16; j += 2) {
        uint32_t hv = (uint32_t)shi[tq + j][c] | ((uint32_t)shi[tq + j + 1][c] << 16);
        uint32_t lv = (uint32_t)slo[tq + j][c] | ((uint32_t)slo[tq + j + 1][c] << 16);
        *(uint32_t*)&g_xT_hi[base + j] = hv;
        *(uint32_t*)&g_xT_lo[base + j] = lv;
    }
}

// ---------------- fold + transpose + bf16-split slice weight ----------------
__global__ void k_prep(const float* __restrict__ Wx, const float* __restrict__ bx,
                       const float* __restrict__ Wsl, const float* __restrict__ bsl) {
    int c = blockIdx.x;        // K index 0..255
    int o = threadIdx.x;       // N index 0..511
    int h = o >> 6, gg = o & 63;
    float s = 0.f;
    #pragma unroll 16
    for (int d = 0; d < 64; d++)
        s += Wx[c*INNER + h*64 + d] * Wsl[d*64 + gg];
    __nv_bfloat16 sh = __float2bfloat16(s);
    g_wslT_hi[o*CC + c] = sh;
    g_wslT_lo[o*CC + c] = __float2bfloat16(s - __bfloat162float(sh));
    if (c == 0) {
        float t = 0.f;
        #pragma unroll 16
        for (int d = 0; d < 64; d++) t += bx[h*64 + d] * Wsl[d*64 + gg];
        g_bsl[o] = t + bsl[gg];
    }
}

// ======= shared-operand mainloop macro pieces (proj/out: M128xN128, warp 64x32) =======
// Per chunk (K=32): load Ahi,Alo,Bhi,Blo once; issue 3 products into same acc.

// ---------------- slice-logits GEMM + softmax (mma.sync) ----------------
// block M128 x N128, K=256 -> 8 chunks of 32. grid (4, 1024).
__global__ __launch_bounds__(256, 2) void k_proj(const float* __restrict__ temp) {
    extern __shared__ char sm[];
    float* stage = (float*)sm;
    uint32_t sb = smem_u32(sm);
    int tid = threadIdx.x;
    int lane = tid & 31, w = tid >> 5;
    int wm = w & 1, wn = w >> 1;
    int tileM = blockIdx.y, y2 = blockIdx.x;
    int row0 = tileM * 128;
    int b = tileM >> 8;
    size_t row0loc = (size_t)(tileM & 255) * 128;

    float acc[4][4][4];
    #pragma unroll
    for (int a = 0; a < 4; a++)
        #pragma unroll
        for (int b2 = 0; b2 < 4; b2++)
            #pragma unroll
            for (int d = 0; d < 4; d++) acc[a][b2][d] = 0.f;

    auto issue = [&](int c) {
        uint32_t base = sb + (c % 3) * 32768;
        int k0 = c * 32;
        #pragma unroll
        for (int i = 0; i < 2; i++) {
            int id = tid + i * 256, r = id >> 2, ce = (id & 3) * 8;
            uint32_t off = SWZ64((uint32_t)(r * 64 + ce * 2));
            size_t asrc = (size_t)(row0 + r) * CC + k0 + ce;
            cpa16(base + off,         g_x_hi + asrc);
            cpa16(base + 8192 + off,  g_x_lo + asrc);
            size_t bsrc = (size_t)(y2*128 + r) * CC + k0 + ce;
            cpa16(base + 16384 + off, g_wslT_hi + bsrc);
            cpa16(base + 24576 + off, g_wslT_lo + bsrc);
        }
        CP_COMMIT();
    };

    issue(0); issue(1);
    for (int c = 0; c < 8; c++) {
        if (c + 1 < 8) CP_WAIT1(); else CP_WAIT0();
        __syncthreads();
        uint32_t base = sb + (c % 3) * 32768;
        int rA = lane & 15;
        #pragma unroll
        for (int kk = 0; kk < 2; kk++) {
            int colb = kk * 32 + (lane >> 4) * 16;
            uint32_t bh4[2][4], bl4[2][4];
            #pragma unroll
            for (int s = 0; s < 2; s++) {
                uint32_t boff = SWZ64((uint32_t)((wn*32 + s*16 + rA) * 64 + colb));
                ldsm4(bh4[s], base + 16384 + boff);
                ldsm4(bl4[s], base + 24576 + boff);
            }
            #pragma unroll
            for (int mi = 0; mi < 4; mi++) {
                uint32_t aoff = SWZ64((uint32_t)((wm*64 + mi*16 + rA) * 64 + colb));
                uint32_t a4[4];
                ldsm4(a4, base + aoff);
                #pragma unroll
                for (int nj = 0; nj < 4; nj++)
                    mma_bf16(acc[mi][nj], a4[0], a4[1], a4[2], a4[3],
                             bh4[nj>>1][nj&1], bh4[nj>>1][(nj&1)+2]);
                #pragma unroll
                for (int nj = 0; nj < 4; nj++)
                    mma_bf16(acc[mi][nj], a4[0], a4[1], a4[2], a4[3],
                             bl4[nj>>1][nj&1], bl4[nj>>1][(nj&1)+2]);
                ldsm4(a4, base + 8192 + aoff);
                #pragma unroll
                for (int nj = 0; nj < 4; nj++)
                    mma_bf16(acc[mi][nj], a4[0], a4[1], a4[2], a4[3],
                             bh4[nj>>1][nj&1], bh4[nj>>1][(nj&1)+2]);
            }
        }
        if (c + 2 < 8) issue(c + 2);
    }
    __syncthreads();

    // frags -> stage
    #pragma unroll
    for (int mi = 0; mi < 4; mi++)
        #pragma unroll
        for (int nj = 0; nj < 4; nj++) {
            int row = wm*64 + mi*16 + (lane >> 2);
            int col = wn*32 + nj*8 + (lane & 3)*2;
            *(float2*)&stage[row*STG + col]     = make_float2(acc[mi][nj][0], acc[mi][nj][1]);
            *(float2*)&stage[(row+8)*STG + col] = make_float2(acc[mi][nj][2], acc[mi][nj][3]);
        }
    __syncthreads();

    // softmax over each head's 64 cols per row
    float rt0 = 1.0f / fminf(fmaxf(temp[y2*2 + 0], 0.1f), 5.0f);
    float rt1 = 1.0f / fminf(fmaxf(temp[y2*2 + 1], 0.1f), 5.0f);
    for (int gi = 0; gi < 32; gi++) {
        int G = w * 32 + gi;
        int r = G >> 1, hh = G & 1;
        float bb0 = g_bsl[y2*128 + hh*64 + lane];
        float bb1 = g_bsl[y2*128 + hh*64 + 32 + lane];
        float rt = hh ? rt1 : rt0;
        float v0 = (stage[r*STG + hh*64 + lane]      + bb0) * rt;
        float v1 = (stage[r*STG + hh*64 + 32 + lane] + bb1) * rt;
        float m = fmaxf(v0, v1);
        #pragma unroll
        for (int o = 16; o; o >>= 1) m = fmaxf(m, __shfl_xor_sync(0xFFFFFFFFu, m, o));
        float e0 = __expf(v0 - m), e1 = __expf(v1 - m);
        float s = e0 + e1;
        #pragma unroll
        for (int o = 16; o; o >>= 1) s += __shfl_xor_sync(0xFFFFFFFFu, s, o);
        float rs = 1.0f / s;
        stage[r*STG + hh*64 + lane]      = e0 * rs;
        stage[r*STG + hh*64 + 32 + lane] = e1 * rs;
    }
    __syncthreads();

    // (a) norm: column sums -> atomic
    if (tid < 128) {
        float s = 0.f;
        #pragma unroll 8
        for (int r = 0; r < 128; r++) s += stage[r*STG + tid];
        int head = tid >> 6, g = tid & 63;
        atomicAdd(&g_norm[(b*8 + y2*2 + head)*64 + g], s);
    }
    // (b) w pair [tok][hg]
    #pragma unroll
    for (int i = 0; i < 16; i++) {
        int lin = tid + i * 256, r = lin >> 5, c4 = (lin & 31) * 4;
        float4 v = *(float4*)&stage[r*STG + c4];
        __nv_bfloat16 hx = __float2bfloat16(v.x), hy = __float2bfloat16(v.y);
        __nv_bfloat16 hz = __float2bfloat16(v.z), hw = __float2bfloat16(v.w);
        __nv_bfloat162 h01(hx, hy), h23(hz, hw);
        __nv_bfloat162 l01 = __floats2bfloat162_rn(v.x - __bfloat162float(hx),
                                                   v.y - __bfloat162float(hy));
        __nv_bfloat162 l23 = __floats2bfloat162_rn(v.z - __bfloat162float(hz),
                                                   v.w - __bfloat162float(hw));
        uint2 uh, ul;
        uh.x = *reinterpret_cast<uint32_t*>(&h01); uh.y = *reinterpret_cast<uint32_t*>(&h23);
        ul.x = *reinterpret_cast<uint32_t*>(&l01); ul.y = *reinterpret_cast<uint32_t*>(&l23);
        size_t idx = (size_t)(row0 + r)*INNER + y2*128 + c4;
        *(uint2*)&g_w_hi[idx] = uh;
        *(uint2*)&g_w_lo[idx] = ul;
    }
    // (c) w^T pair [bh][g][n]
    {
        int cc = tid >> 1, half = tid & 1;
        int head = cc >> 6, g = cc & 63;
        size_t base = ((size_t)(b*8 + y2*2 + head) * 64 + g) * (size_t)NTOK + row0loc;
        #pragma unroll
        for (int i = 0; i < 32; i++) {
            int r = half*64 + 2*i;
            float v0 = stage[r*STG + cc], v1 = stage[(r+1)*STG + cc];
            __nv_bfloat16 h0 = __float2bfloat16(v0), h1 = __float2bfloat16(v1);
            uint32_t hw2 = (uint32_t)*(uint16_t*)&h0 | ((uint32_t)*(uint16_t*)&h1 << 16);
            __nv_bfloat16 l0 = __float2bfloat16(v0 - __bfloat162float(h0));
            __nv_bfloat16 l1 = __float2bfloat16(v1 - __bfloat162float(h1));
            uint32_t lw2 = (uint32_t)*(uint16_t*)&l0 | ((uint32_t)*(uint16_t*)&l1 << 16);
            *(uint32_t*)&g_wT_hi[base + r] = hw2;
            *(uint32_t*)&g_wT_lo[base + r] = lw2;
        }
    }
}

// ---------------- pooling GEMM: P[bh][g][c] = sum_n w[n,g]*x[n,c] ----------------
// block M64(g) x N128(c), grid (32 bh, 16 kc, 2 cb). 64 chunks of 32 k each.
__global__ __launch_bounds__(256, 2) void k_poolg() {
    extern __shared__ char sm[];
    uint32_t sb = smem_u32(sm);
    int tid = threadIdx.x;
    int lane = tid & 31, w = tid >> 5;
    int wm = w & 1, wn = w >> 1;
    int bh = blockIdx.x, kc = blockIdx.y, cb = blockIdx.z;
    int b = bh >> 3;
    size_t nbase = (size_t)kc * 2048;
    const __nv_bfloat16* Ahi = g_wT_hi + (size_t)bh * 64 * NTOK;
    const __nv_bfloat16* Alo = g_wT_lo + (size_t)bh * 64 * NTOK;
    const __nv_bfloat16* Bhi = g_xT_hi + ((size_t)b * CC + cb * 128) * NTOK;
    const __nv_bfloat16* Blo = g_xT_lo + ((size_t)b * CC + cb * 128) * NTOK;

    float acc[2][4][4];
    #pragma unroll
    for (int a = 0; a < 2; a++)
        #pragma unroll
        for (int b2 = 0; b2 < 4; b2++)
            #pragma unroll
            for (int d = 0; d < 4; d++) acc[a][b2][d] = 0.f;

    auto issue = [&](int c) {
        uint32_t base = sb + (c % 3) * 24576;
        size_t k0 = nbase + c * 32;
        {   // A tiles: 64 rows x 32 -> 4KB each
            int r = tid >> 2, ce = (tid & 3) * 8;
            uint32_t off = SWZ64((uint32_t)(r * 64 + ce * 2));
            size_t asrc = (size_t)r * NTOK + k0 + ce;
            cpa16(base + off,        Ahi + asrc);
            cpa16(base + 4096 + off, Alo + asrc);
        }
        #pragma unroll
        for (int i = 0; i < 2; i++) {   // B tiles: 128 rows x 32 -> 8KB each
            int id = tid + i * 256, r = id >> 2, ce = (id & 3) * 8;
            uint32_t off = SWZ64((uint32_t)(r * 64 + ce * 2));
            size_t bsrc = (size_t)r * NTOK + k0 + ce;
            cpa16(base + 8192 + off,  Bhi + bsrc);
            cpa16(base + 16384 + off, Blo + bsrc);
        }
        CP_COMMIT();
    };

    issue(0); issue(1);
    for (int c = 0; c < 64; c++) {
        if (c + 1 < 64) CP_WAIT1(); else CP_WAIT0();
        __syncthreads();
        uint32_t base = sb + (c % 3) * 24576;
        int rA = lane & 15;
        #pragma unroll
        for (int kk = 0; kk < 2; kk++) {
            int colb = kk * 32 + (lane >> 4) * 16;
            uint32_t bh4[2][4], bl4[2][4];
            #pragma unroll
            for (int s = 0; s < 2; s++) {
                uint32_t boff = SWZ64((uint32_t)((wn*32 + s*16 + rA) * 64 + colb));
                ldsm4(bh4[s], base + 8192 + boff);
                ldsm4(bl4[s], base + 16384 + boff);
            }
            #pragma unroll
            for (int mi = 0; mi < 2; mi++) {
                uint32_t aoff = SWZ64((uint32_t)((wm*32 + mi*16 + rA) * 64 + colb));
                uint32_t a4[4];
                ldsm4(a4, base + aoff);
                #pragma unroll
                for (int nj = 0; nj < 4; nj++)
                    mma_bf16(acc[mi][nj], a4[0], a4[1], a4[2], a4[3],
                             bh4[nj>>1][nj&1], bh4[nj>>1][(nj&1)+2]);
                #pragma unroll
                for (int nj = 0; nj < 4; nj++)
                    mma_bf16(acc[mi][nj], a4[0], a4[1], a4[2], a4[3],
                             bl4[nj>>1][nj&1], bl4[nj>>1][(nj&1)+2]);
                ldsm4(a4, base + 4096 + aoff);
                #pragma unroll
                for (int nj = 0; nj < 4; nj++)
                    mma_bf16(acc[mi][nj], a4[0], a4[1], a4[2], a4[3],
                             bh4[nj>>1][nj&1], bh4[nj>>1][(nj&1)+2]);
            }
        }
        if (c + 2 < 64) issue(c + 2);
    }

    #pragma unroll
    for (int mi = 0; mi < 2; mi++)
        #pragma unroll
        for (int nj = 0; nj < 4; nj++) {
            int row = wm*32 + mi*16 + (lane >> 2);
            int col = cb*128 + wn*32 + nj*8 + (lane & 3)*2;
            int base = bh*16384 + row*256 + col;
            atomicAdd(&g_P[base],            acc[mi][nj][0]);
            atomicAdd(&g_P[base + 1],        acc[mi][nj][1]);
            atomicAdd(&g_P[base + 8*256],    acc[mi][nj][2]);
            atomicAdd(&g_P[base + 8*256 + 1],acc[mi][nj][3]);
        }
}

// ---------------- fold: ST[bh][g][d] = P@Wfx + bfx*norm ----------------
__global__ void k_stok(const float* __restrict__ Wfx, const float* __restrict__ bfx) {
    int bh = blockIdx.x;
    int h = bh & 7;
    int tid = threadIdx.x;
    __shared__ float wf[64][65], pp[64][65];
    float acc[16];
    #pragma unroll
    for (int j = 0; j < 16; j++) acc[j] = 0.f;
    int g = tid >> 2, dq = tid & 3;
    for (int c0 = 0; c0 < 4; c0++) {
        #pragma unroll
        for (int i = 0; i < 16; i++) {
            int id = tid + i * 256;
            int r = id >> 6, cl = id & 63;
            wf[r][cl] = Wfx[(c0*64 + r) * INNER + h*64 + cl];
            pp[r][cl] = g_P[bh*16384 + r*256 + c0*64 + cl];
        }
        __syncthreads();
        for (int cl = 0; cl < 64; cl++) {
            float pv = pp[g][cl];
            #pragma unroll
            for (int j = 0; j < 16; j++)
                acc[j] += pv * wf[cl][dq*16 + j];
        }
        __syncthreads();
    }
    float nrm = g_norm[bh*64 + g];
    #pragma unroll
    for (int j = 0; j < 16; j++) {
        int d = dq*16 + j;
        g_st[bh*4096 + g*64 + d] = acc[j] + bfx[h*64 + d] * nrm;
    }
}

// ---------------- tiny attention over slice tokens ----------------
__global__ void k_attn(const float* __restrict__ Wq, const float* __restrict__ Wk,
                       const float* __restrict__ Wv) {
    int bh = blockIdx.x;
    int tid = threadIdx.x;
    __shared__ float sn[64][64];
    __shared__ float ks[64][64];
    __shared__ float nrm[64];
    if (tid < 64) nrm[tid] = g_norm[bh * 64 + tid] + 1e-5f;
    __syncthreads();
    #pragma unroll
    for (int it = 0; it < 16; it++) {
        int idx = tid + it * 256;
        int g2 = idx >> 6;
        sn[g2][idx & 63] = g_st[bh * 4096 + idx] / nrm[g2];
    }
    __syncthreads();
    #pragma unroll
    for (int it = 0; it < 16; it++) {
        int idx = tid + it * 256;
        int g2 = idx >> 6, d2 = idx & 63;
        float s0 = 0, s1 = 0, s2 = 0, s3 = 0;
        #pragma unroll
        for (int d = 0; d < 64; d += 4) {
            s0 += sn[g2][d]   * Wk[(d)   * 64 + d2];
            s1 += sn[g2][d+1] * Wk[(d+1) * 64 + d2];
            s2 += sn[g2][d+2] * Wk[(d+2) * 64 + d2];
            s3 += sn[g2][d+3] * Wk[(d+3) * 64 + d2];
        }
        ks[g2][d2] = (s0 + s1) + (s2 + s3);
    }
    __syncthreads();
    float tv[64];
    if (tid < 64) {
        int g2 = tid;
        float q[64];
        #pragma unroll
        for (int d2 = 0; d2 < 64; d2++) {
            float s0 = 0, s1 = 0, s2 = 0, s3 = 0;
            #pragma unroll
            for (int d = 0; d < 64; d += 4) {
                s0 += sn[g2][d]   * Wq[(d)   * 64 + d2];
                s1 += sn[g2][d+1] * Wq[(d+1) * 64 + d2];
                s2 += sn[g2][d+2] * Wq[(d+2) * 64 + d2];
                s3 += sn[g2][d+3] * Wq[(d+3) * 64 + d2];
            }
            q[d2] = (s0 + s1) + (s2 + s3);
        }
        float p[64];
        float mx = -1e30f;
        #pragma unroll
        for (int j = 0; j < 64; j++) {
            float s0 = 0, s1 = 0, s2 = 0, s3 = 0;
            #pragma unroll
            for (int d = 0; d < 64; d += 4) {
                s0 += q[d]   * ks[j][d];
                s1 += q[d+1] * ks[j][d+1];
                s2 += q[d+2] * ks[j][d+2];
                s3 += q[d+3] * ks[j][d+3];
            }
            float s = ((s0 + s1) + (s2 + s3)) * 0.125f;
            p[j] = s;
            mx = fmaxf(mx, s);
        }
        float sum = 0.f;
        #pragma unroll
        for (int j = 0; j < 64; j++) { p[j] = __expf(p[j] - mx); sum += p[j]; }
        float rs = 1.0f / sum;
        #pragma unroll
        for (int e = 0; e < 64; e++) {
            float s0 = 0, s1 = 0, s2 = 0, s3 = 0;
            #pragma unroll
            for (int j = 0; j < 64; j += 4) {
                s0 += p[j]   * sn[j][e];
                s1 += p[j+1] * sn[j+1][e];
                s2 += p[j+2] * sn[j+2][e];
                s3 += p[j+3] * sn[j+3][e];
            }
            tv[e] = ((s0 + s1) + (s2 + s3)) * rs;
        }
    }
    __syncthreads();
    if (tid < 64) {
        #pragma unroll
        for (int e = 0; e < 64; e++) ks[tid][e] = tv[e];
    }
    __syncthreads();
    #pragma unroll
    for (int it = 0; it < 16; it++) {
        int idx = tid + it * 256;
        int g2 = idx >> 6, d2 = idx & 63;
        float s0 = 0, s1 = 0, s2 = 0, s3 = 0;
        #pragma unroll
        for (int e = 0; e < 64; e += 4) {
            s0 += ks[g2][e]   * Wv[(e)   * 64 + d2];
            s1 += ks[g2][e+1] * Wv[(e+1) * 64 + d2];
            s2 += ks[g2][e+2] * Wv[(e+2) * 64 + d2];
            s3 += ks[g2][e+3] * Wv[(e+3) * 64 + d2];
        }
        g_os[bh * 4096 + idx] = (s0 + s1) + (s2 + s3);
    }
}

// ---------------- fold out_slice into W_out: W_eff^T pair [b][n=256][k=512] ----------------
__global__ void k_weff(const float* __restrict__ Wout) {
    int blk = blockIdx.x;           // b*512 + row
    int b = blk >> 9;
    int row = blk & 511;            // k index: h*64+g
    int h = row >> 6;
    int tid = threadIdx.x;          // n index = c (256)
    __shared__ float osr[64];
    if (tid < 64) osr[tid] = g_os[(b*8 + h) * 4096 + (row & 63) * 64 + tid];
    __syncthreads();
    float s = 0.f;
    #pragma unroll 16
    for (int d = 0; d < 64; d++)
        s += osr[d] * Wout[(h*64 + d) * CC + tid];
    __nv_bfloat16 sh = __float2bfloat16(s);
    size_t idx = (size_t)b * (CC*INNER) + (size_t)tid * INNER + row;
    g_weffT_hi[idx] = sh;
    g_weffT_lo[idx] = __float2bfloat16(s - __bfloat162float(sh));
}

// ---------------- output GEMM (mma.sync): y = w @ W_eff[b] + b_out ----------------
// block M128 x N128, K=512 -> 16 chunks of 32. grid (2, 1024): ct fast-varying.
__global__ __launch_bounds__(256, 2) void k_out(const float* __restrict__ bout,
                                                float* __restrict__ y) {
    extern __shared__ char sm[];
    float* stage = (float*)sm;
    uint32_t sb = smem_u32(sm);
    int tid = threadIdx.x;
    int lane = tid & 31, w = tid >> 5;
    int wm = w & 1, wn = w >> 1;
    int tileM = blockIdx.y, ct = blockIdx.x;
    int row0 = tileM * 128;
    int b = tileM >> 8;

    float acc[4][4][4];
    #pragma unroll
    for (int a = 0; a < 4; a++)
        #pragma unroll
        for (int bb2 = 0; bb2 < 4; bb2++)
            #pragma unroll
            for (int d = 0; d < 4; d++) acc[a][bb2][d] = 0.f;

    auto issue = [&](int c) {
        uint32_t base = sb + (c % 3) * 32768;
        int k0 = c * 32;
        #pragma unroll
        for (int i = 0; i < 2; i++) {
            int id = tid + i * 256, r = id >> 2, ce = (id & 3) * 8;
            uint32_t off = SWZ64((uint32_t)(r * 64 + ce * 2));
            size_t asrc = (size_t)(row0 + r) * INNER + k0 + ce;
            cpa16(base + off,        g_w_hi + asrc);
            cpa16(base + 8192 + off, g_w_lo + asrc);
            size_t bsrc = (size_t)b * (CC*INNER) + (size_t)(ct*128 + r) * INNER + k0 + ce;
            cpa16(base + 16384 + off, g_weffT_hi + bsrc);
            cpa16(base + 24576 + off, g_weffT_lo + bsrc);
        }
        CP_COMMIT();
    };

    issue(0); issue(1);
    for (int c = 0; c < 16; c++) {
        if (c + 1 < 16) CP_WAIT1(); else CP_WAIT0();
        __syncthreads();
        uint32_t base = sb + (c % 3) * 32768;
        int rA = lane & 15;
        #pragma unroll
        for (int kk = 0; kk < 2; kk++) {
            int colb = kk * 32 + (lane >> 4) * 16;
            uint32_t bh4[2][4], bl4[2][4];
            #pragma unroll
            for (int s = 0; s < 2; s++) {
                uint32_t boff = SWZ64((uint32_t)((wn*32 + s*16 + rA) * 64 + colb));
                ldsm4(bh4[s], base + 16384 + boff);
                ldsm4(bl4[s], base + 24576 + boff);
            }
            #pragma unroll
            for (int mi = 0; mi < 4; mi++) {
                uint32_t aoff = SWZ64((uint32_t)((wm*64 + mi*16 + rA) * 64 + colb));
                uint32_t a4[4];
                ldsm4(a4, base + aoff);
                #pragma unroll
                for (int nj = 0; nj < 4; nj++)
                    mma_bf16(acc[mi][nj], a4[0], a4[1], a4[2], a4[3],
                             bh4[nj>>1][nj&1], bh4[nj>>1][(nj&1)+2]);
                #pragma unroll
                for (int nj = 0; nj < 4; nj++)
                    mma_bf16(acc[mi][nj], a4[0], a4[1], a4[2], a4[3],
                             bl4[nj>>1][nj&1], bl4[nj>>1][(nj&1)+2]);
                ldsm4(a4, base + 8192 + aoff);
                #pragma unroll
                for (int nj = 0; nj < 4; nj++)
                    mma_bf16(acc[mi][nj], a4[0], a4[1], a4[2], a4[3],
                             bh4[nj>>1][nj&1], bh4[nj>>1][(nj&1)+2]);
            }
        }
        if (c + 2 < 16) issue(c + 2);
    }
    __syncthreads();

    #pragma unroll
    for (int mi = 0; mi < 4; mi++)
        #pragma unroll
        for (int nj = 0; nj < 4; nj++) {
            int row = wm*64 + mi*16 + (lane >> 2);
            int col = wn*32 + nj*8 + (lane & 3)*2;
            *(float2*)&stage[row*STG + col]     = make_float2(acc[mi][nj][0], acc[mi][nj][1]);
            *(float2*)&stage[(row+8)*STG + col] = make_float2(acc[mi][nj][2], acc[mi][nj][3]);
        }
    __syncthreads();
    #pragma unroll
    for (int i = 0; i < 16; i++) {
        int lin = tid + i * 256, r = lin >> 5, c4 = (lin & 31) * 4;
        float4 v = *(float4*)&stage[r*STG + c4];
        float4 bv = *(const float4*)&bout[ct*128 + c4];
        v.x += bv.x; v.y += bv.y; v.z += bv.z; v.w += bv.w;
        *(float4*)&y[(size_t)(row0 + r)*CC + ct*128 + c4] = v;
    }
}

// ---------------- launch ----------------
extern "C" void kernel_launch(void* const* d_in, const int* in_sizes, int n_in,
                              void* d_out, int out_size) {
    const float* x    = (const float*)d_in[0];
    const float* Wfx  = (const float*)d_in[1];
    const float* bfx  = (const float*)d_in[2];
    const float* Wx   = (const float*)d_in[3];
    const float* bx   = (const float*)d_in[4];
    const float* Wsl  = (const float*)d_in[5];
    const float* bsl  = (const float*)d_in[6];
    const float* temp = (const float*)d_in[7];
    const float* Wq   = (const float*)d_in[8];
    const float* Wk   = (const float*)d_in[9];
    const float* Wv   = (const float*)d_in[10];
    const float* Wout = (const float*)d_in[11];
    const float* bout = (const float*)d_in[12];
    float* y = (float*)d_out;

    cudaFuncSetAttribute(k_proj,  cudaFuncAttributeMaxDynamicSharedMemorySize, GSMEM);
    cudaFuncSetAttribute(k_poolg, cudaFuncAttributeMaxDynamicSharedMemorySize, PGSMEM);
    cudaFuncSetAttribute(k_out,   cudaFuncAttributeMaxDynamicSharedMemorySize, GSMEM);

    k_zero<<<2048, 256>>>();
    k_prep<<<CC, 512>>>(Wx, bx, Wsl, bsl);
    k_split<<<dim3(TOK/64, 4), 256>>>(x);
    k_proj<<<dim3(4, TOK/128), 256, GSMEM>>>(temp);
    k_poolg<<<dim3(32, 16, 2), 256, PGSMEM>>>();
    k_stok<<<32, 256>>>(Wfx, bfx);
    k_attn<<<32, 256>>>(Wq, Wk, Wv);
    k_weff<<<2048, 256>>>(Wout);
    k_out<<<dim3(2, TOK/128), 256, GSMEM>>>(bout, y);
}